// round 16
// baseline (speedup 1.0000x reference)
#include <cuda_runtime.h>

#define W_IMG 1024
#define H_IMG 1024
#define C_IMG 3
#define PLANE (H_IMG * W_IMG)

#define RPT 4                 // rows per thread
#define WARPS 8               // 256 threads -> tile 32 wide x 32 tall
#define BLOCK (32 * WARPS)

__global__ __launch_bounds__(BLOCK, 8) void homography_warp_kernel(
    const float* __restrict__ img,    // [N, C, H, W]
    const float* __restrict__ homo,   // [N, 3, 3]
    float* __restrict__ out)          // [N, C, H, W]
{
    const int n    = blockIdx.z;
    const int lane = threadIdx.x & 31;
    const int wrp  = threadIdx.x >> 5;
    const int w    = blockIdx.x * 32 + lane;
    const int h0   = (blockIdx.y * WARPS + wrp) * RPT;

    __shared__ float Hs[9];
    if (threadIdx.x < 9) Hs[threadIdx.x] = homo[n * 9 + threadIdx.x];
    __syncthreads();

    const float gx  = (float)w  * (2.0f / 1023.0f) - 1.0f;
    const float gy0 = (float)h0 * (2.0f / 1023.0f) - 1.0f;
    const float dg  = 2.0f / 1023.0f;

    // Transform at row h0; per-row increment = second column of H * dg.
    float Xr = Hs[0] * gx + Hs[1] * gy0 + Hs[2];
    float Yr = Hs[3] * gx + Hs[4] * gy0 + Hs[5];
    float Zr = Hs[6] * gx + Hs[7] * gy0 + Hs[8];
    const float dX = Hs[1] * dg;
    const float dY = Hs[4] * dg;
    const float dZ = Hs[7] * dg;

    int   off[RPT];            // y0*1024 + x0 (packed)
    float fx[RPT], fy[RPT];    // fractional weights (wx1, wy1)
    bool  inter = true;

    {
        float Xi = Xr, Yi = Yr, Zi = Zr;
#pragma unroll
        for (int i = 0; i < RPT; i++) {
            const float inv = __fdividef(1.0f, Zi);
            const float x = (Xi * inv + 1.0f) * (0.5f * (float)(W_IMG - 1));
            const float y = (Yi * inv + 1.0f) * (0.5f * (float)(H_IMG - 1));
            const float x0f = floorf(x);
            const float y0f = floorf(y);
            const int x0 = (int)x0f;
            const int y0 = (int)y0f;
            fx[i] = x - x0f;
            fy[i] = y - y0f;
            off[i] = y0 * W_IMG + x0;
            inter &= (x0 >= 0) & (x0 <= W_IMG - 2) & (y0 >= 0) & (y0 <= H_IMG - 2);
            Xi += dX; Yi += dY; Zi += dZ;
        }
    }

    // Channel-1-anchored bases: channel offsets +-PLANE (4MB) fit LDG/STG immediates.
    const float* pc1 = img + n * (C_IMG * PLANE) + PLANE;
    float*       oc1 = out + n * (C_IMG * PLANE) + PLANE + h0 * W_IMG + w;

    if (__all_sync(0xFFFFFFFFu, inter)) {
        // ---- fast path: vertical tap-pair reuse, lerp blending ----
        bool share[RPT];
        share[0] = false;
#pragma unroll
        for (int i = 1; i < RPT; i++)
            share[i] = (off[i] == off[i - 1] + W_IMG);

#pragma unroll
        for (int c = -1; c <= 1; c++) {
            const int co = c * PLANE;
            float t0 = 0.0f, t1 = 0.0f;
#pragma unroll
            for (int i = 0; i < RPT; i++) {
                const float* p = pc1 + off[i] + co;
                if (i == 0 || !share[i]) {        // predicated reload when chain breaks
                    t0 = p[0];
                    t1 = p[1];
                }
                const float b0 = p[W_IMG];
                const float b1 = p[W_IMG + 1];
                const float vt = fmaf(fx[i], t1 - t0, t0);
                const float vb = fmaf(fx[i], b1 - b0, b0);
                oc1[co + i * W_IMG] = fmaf(fy[i], vb - vt, vt);
                t0 = b0; t1 = b1;                 // candidate reuse for next row
            }
        }
    } else {
        // ---- slow path (rare boundary warps): recompute; full zeros-padding ----
#pragma unroll 1
        for (int i = 0; i < RPT; i++) {
            const float inv = __fdividef(1.0f, Zr);
            const float x = (Xr * inv + 1.0f) * (0.5f * (float)(W_IMG - 1));
            const float y = (Yr * inv + 1.0f) * (0.5f * (float)(H_IMG - 1));
            Xr += dX; Yr += dY; Zr += dZ;

            const float x0f = floorf(x);
            const float y0f = floorf(y);
            const int xa = (int)x0f, ya = (int)y0f;
            const int xb = xa + 1,   yb = ya + 1;

            const float wx1 = x - x0f, wx0 = 1.0f - wx1;
            const float wy1 = y - y0f, wy0 = 1.0f - wy1;

            const bool vx0 = (xa >= 0) & (xa < W_IMG);
            const bool vx1 = (xb >= 0) & (xb < W_IMG);
            const bool vy0 = (ya >= 0) & (ya < H_IMG);
            const bool vy1 = (yb >= 0) & (yb < H_IMG);

            const int x0c = min(max(xa, 0), W_IMG - 1);
            const int x1c = min(max(xb, 0), W_IMG - 1);
            const int y0c = min(max(ya, 0), H_IMG - 1);
            const int y1c = min(max(yb, 0), H_IMG - 1);

            const float w00 = (vx0 && vy0) ? (wx0 * wy0) : 0.0f;
            const float w01 = (vx1 && vy0) ? (wx1 * wy0) : 0.0f;
            const float w10 = (vx0 && vy1) ? (wx0 * wy1) : 0.0f;
            const float w11 = (vx1 && vy1) ? (wx1 * wy1) : 0.0f;

            const int r0 = y0c * W_IMG;
            const int r1 = y1c * W_IMG;

#pragma unroll
            for (int c = -1; c <= 1; c++) {
                const int co = c * PLANE;
                const float v = pc1[co + r0 + x0c] * w00
                              + pc1[co + r0 + x1c] * w01
                              + pc1[co + r1 + x0c] * w10
                              + pc1[co + r1 + x1c] * w11;
                oc1[co + i * W_IMG] = v;
            }
        }
    }
}

extern "C" void kernel_launch(void* const* d_in, const int* in_sizes, int n_in,
                              void* d_out, int out_size) {
    const float* patch_src    = (const float*)d_in[0];  // [16,3,1024,1024]
    const float* dst_homo_src = (const float*)d_in[1];  // [16,3,3]
    float* out = (float*)d_out;

    // Maximize L1D capacity: request minimal smem carveout (kernel uses 36 B).
    // Host-side attribute set; deterministic, allocation-free, capture-safe.
    cudaFuncSetAttribute(homography_warp_kernel,
                         cudaFuncAttributePreferredSharedMemoryCarveout, 0);

    dim3 grid(W_IMG / 32, H_IMG / (WARPS * RPT), 16);
    homography_warp_kernel<<<grid, BLOCK>>>(patch_src, dst_homo_src, out);
}

// round 17
// speedup vs baseline: 1.0316x; 1.0316x over previous
#include <cuda_runtime.h>

#define W_IMG 1024
#define H_IMG 1024
#define C_IMG 3
#define PLANE (H_IMG * W_IMG)

#define RPT 4                 // rows per thread
#define WARPS 8               // 256 threads -> tile 32 wide x 32 tall
#define BLOCK (32 * WARPS)

__global__ __launch_bounds__(BLOCK, 8) void homography_warp_kernel(
    const float* __restrict__ img,    // [N, C, H, W]
    const float* __restrict__ homo,   // [N, 3, 3]
    float* __restrict__ out)          // [N, C, H, W]
{
    const int n    = blockIdx.z;
    const int lane = threadIdx.x & 31;
    const int wrp  = threadIdx.x >> 5;
    const int w    = blockIdx.x * 32 + lane;
    const int h0   = (blockIdx.y * WARPS + wrp) * RPT;

    __shared__ float Hs[9];
    if (threadIdx.x < 9) Hs[threadIdx.x] = homo[n * 9 + threadIdx.x];
    __syncthreads();

    const float gx  = (float)w  * (2.0f / 1023.0f) - 1.0f;
    const float gy0 = (float)h0 * (2.0f / 1023.0f) - 1.0f;
    const float dg  = 2.0f / 1023.0f;

    // Transform at row h0; per-row increment = second column of H * dg.
    float Xr = Hs[0] * gx + Hs[1] * gy0 + Hs[2];
    float Yr = Hs[3] * gx + Hs[4] * gy0 + Hs[5];
    float Zr = Hs[6] * gx + Hs[7] * gy0 + Hs[8];
    const float dX = Hs[1] * dg;
    const float dY = Hs[4] * dg;
    const float dZ = Hs[7] * dg;

    int   off[RPT];            // y0*1024 + x0 (packed)
    float fx[RPT], fy[RPT];    // fractional weights (wx1, wy1)
    bool  inter = true;

    {
        float Xi = Xr, Yi = Yr, Zi = Zr;
#pragma unroll
        for (int i = 0; i < RPT; i++) {
            const float inv = __fdividef(1.0f, Zi);
            const float x = (Xi * inv + 1.0f) * (0.5f * (float)(W_IMG - 1));
            const float y = (Yi * inv + 1.0f) * (0.5f * (float)(H_IMG - 1));
            const float x0f = floorf(x);
            const float y0f = floorf(y);
            const int x0 = (int)x0f;
            const int y0 = (int)y0f;
            fx[i] = x - x0f;
            fy[i] = y - y0f;
            off[i] = y0 * W_IMG + x0;
            inter &= (x0 >= 0) & (x0 <= W_IMG - 2) & (y0 >= 0) & (y0 <= H_IMG - 2);
            Xi += dX; Yi += dY; Zi += dZ;
        }
    }

    // Channel-1-anchored bases: channel offsets +-PLANE (4MB) fit LDG/STG immediates.
    const float* pc1 = img + n * (C_IMG * PLANE) + PLANE;
    float*       oc1 = out + n * (C_IMG * PLANE) + PLANE + h0 * W_IMG + w;

    if (__all_sync(0xFFFFFFFFu, inter)) {
        // ---- fast path: vertical tap-pair reuse, lerp blending ----
        bool share[RPT];
        share[0] = false;
#pragma unroll
        for (int i = 1; i < RPT; i++)
            share[i] = (off[i] == off[i - 1] + W_IMG);

#pragma unroll
        for (int c = -1; c <= 1; c++) {
            const int co = c * PLANE;
            float t0 = 0.0f, t1 = 0.0f;
#pragma unroll
            for (int i = 0; i < RPT; i++) {
                const float* p = pc1 + off[i] + co;
                if (i == 0 || !share[i]) {        // predicated reload when chain breaks
                    t0 = p[0];
                    t1 = p[1];
                }
                const float b0 = p[W_IMG];
                const float b1 = p[W_IMG + 1];
                const float vt = fmaf(fx[i], t1 - t0, t0);
                const float vb = fmaf(fx[i], b1 - b0, b0);
                oc1[co + i * W_IMG] = fmaf(fy[i], vb - vt, vt);
                t0 = b0; t1 = b1;                 // candidate reuse for next row
            }
        }
    } else {
        // ---- slow path (rare boundary warps): recompute; full zeros-padding ----
#pragma unroll 1
        for (int i = 0; i < RPT; i++) {
            const float inv = __fdividef(1.0f, Zr);
            const float x = (Xr * inv + 1.0f) * (0.5f * (float)(W_IMG - 1));
            const float y = (Yr * inv + 1.0f) * (0.5f * (float)(H_IMG - 1));
            Xr += dX; Yr += dY; Zr += dZ;

            const float x0f = floorf(x);
            const float y0f = floorf(y);
            const int xa = (int)x0f, ya = (int)y0f;
            const int xb = xa + 1,   yb = ya + 1;

            const float wx1 = x - x0f, wx0 = 1.0f - wx1;
            const float wy1 = y - y0f, wy0 = 1.0f - wy1;

            const bool vx0 = (xa >= 0) & (xa < W_IMG);
            const bool vx1 = (xb >= 0) & (xb < W_IMG);
            const bool vy0 = (ya >= 0) & (ya < H_IMG);
            const bool vy1 = (yb >= 0) & (yb < H_IMG);

            const int x0c = min(max(xa, 0), W_IMG - 1);
            const int x1c = min(max(xb, 0), W_IMG - 1);
            const int y0c = min(max(ya, 0), H_IMG - 1);
            const int y1c = min(max(yb, 0), H_IMG - 1);

            const float w00 = (vx0 && vy0) ? (wx0 * wy0) : 0.0f;
            const float w01 = (vx1 && vy0) ? (wx1 * wy0) : 0.0f;
            const float w10 = (vx0 && vy1) ? (wx0 * wy1) : 0.0f;
            const float w11 = (vx1 && vy1) ? (wx1 * wy1) : 0.0f;

            const int r0 = y0c * W_IMG;
            const int r1 = y1c * W_IMG;

#pragma unroll
            for (int c = -1; c <= 1; c++) {
                const int co = c * PLANE;
                const float v = pc1[co + r0 + x0c] * w00
                              + pc1[co + r0 + x1c] * w01
                              + pc1[co + r1 + x0c] * w10
                              + pc1[co + r1 + x1c] * w11;
                oc1[co + i * W_IMG] = v;
            }
        }
    }
}

extern "C" void kernel_launch(void* const* d_in, const int* in_sizes, int n_in,
                              void* d_out, int out_size) {
    const float* patch_src    = (const float*)d_in[0];  // [16,3,1024,1024]
    const float* dst_homo_src = (const float*)d_in[1];  // [16,3,3]
    float* out = (float*)d_out;

    dim3 grid(W_IMG / 32, H_IMG / (WARPS * RPT), 16);
    homography_warp_kernel<<<grid, BLOCK>>>(patch_src, dst_homo_src, out);
}